// round 1
// baseline (speedup 1.0000x reference)
#include <cuda_runtime.h>
#include <cuda_bf16.h>
#include <math.h>

#define NLOC 49104
#define BATCH 16
#define MAXDET 1000
#define CAND 4096
#define NBINS 2048

// Level tables: HS = 192,96,48,24,12 ; strides 8,16,32,64,128
// offsets: 0, 36864, 46080, 48384, 48960, 49104

struct Ptrs {
    const float* cls[5];
    const float* reg[5];
    const float* tc[5];
    const float* tr[5];
};

// ------------------------- scratch (__device__ globals) -------------------------
__device__ unsigned long long g_keys[BATCH * NLOC];        // 6.28 MB
__device__ int                g_tk_loc[BATCH * MAXDET];
__device__ float              g_tk_score[BATCH * MAXDET];
__device__ float              g_tk_box[BATCH * MAXDET * 5];
__device__ int                g_tk_cls[BATCH * MAXDET];
__device__ unsigned char      g_tk_valid[BATCH * MAXDET];
__device__ float              g_nms_box[BATCH * MAXDET * 4];
__device__ unsigned long long g_mask[BATCH * MAXDET * 16]; // 2 MB

// ------------------------- helpers -------------------------
__device__ __forceinline__ void loc_to_level(int loc, int& lvl, int& hh, int& local,
                                             int& stride, int& h) {
    if (loc < 36864)      { lvl = 0; hh = 36864; local = loc;         stride = 8;   h = 192; }
    else if (loc < 46080) { lvl = 1; hh = 9216;  local = loc - 36864; stride = 16;  h = 96;  }
    else if (loc < 48384) { lvl = 2; hh = 2304;  local = loc - 46080; stride = 32;  h = 48;  }
    else if (loc < 48960) { lvl = 3; hh = 576;   local = loc - 48384; stride = 64;  h = 24;  }
    else                  { lvl = 4; hh = 144;   local = loc - 48960; stride = 128; h = 12;  }
}

// ------------------------- K1: scores -> sort keys -------------------------
__global__ void k_scores(Ptrs P) {
    int gid = blockIdx.x * blockDim.x + threadIdx.x;
    if (gid >= BATCH * NLOC) return;
    int b = gid / NLOC;
    int loc = gid - b * NLOC;

    int lvl, hh, local, stride, h;
    loc_to_level(loc, lvl, hh, local, stride, h);

    const float* q = P.cls[lvl] + (size_t)b * 15 * hh + local;
    float m = q[0];
#pragma unroll
    for (int c = 1; c < 15; c++) {
        float v = q[(size_t)c * hh];
        m = fmaxf(m, v);
    }
    // correctly-rounded f32 sigmoid via double
    double s = 1.0 / (1.0 + exp(-(double)m));
    float sf = (float)s;
    unsigned int bits = __float_as_uint(sf);
    // key: (score_bits, ~loc) so descending sort gives stable (score desc, idx asc)
    g_keys[gid] = ((unsigned long long)bits << 32) | (unsigned int)(~(unsigned int)loc);
}

// ------------------------- K2: per-batch exact top-1000 (hist + bitonic) -------------------------
__global__ void __launch_bounds__(1024) k_select() {
    __shared__ unsigned int hist[NBINS];
    __shared__ unsigned long long cand[CAND];
    __shared__ int s_cnt;
    __shared__ int s_thr;

    int b = blockIdx.x;
    int tid = threadIdx.x;

    hist[tid] = 0u;
    hist[tid + 1024] = 0u;
    if (tid == 0) { s_cnt = 0; s_thr = 0; }
    __syncthreads();

    const unsigned long long* kb = g_keys + (size_t)b * NLOC;

    for (int i = tid; i < NLOC; i += 1024) {
        float s = __uint_as_float((unsigned int)(kb[i] >> 32));
        int bu = (int)(s * (float)NBINS);
        bu = min(NBINS - 1, max(0, bu));
        atomicAdd(&hist[bu], 1u);
    }
    __syncthreads();

    // suffix scan (Hillis-Steele): hist[i] = count of elements in buckets >= i
    for (int off = 1; off < NBINS; off <<= 1) {
        unsigned v0 = hist[tid]        + ((tid + off        < NBINS) ? hist[tid + off]        : 0u);
        unsigned v1 = hist[tid + 1024] + ((tid + 1024 + off < NBINS) ? hist[tid + 1024 + off] : 0u);
        __syncthreads();
        hist[tid] = v0;
        hist[tid + 1024] = v1;
        __syncthreads();
    }

    // threshold bucket: smallest t with suffix(t) >= 1000 and suffix(t+1) < 1000
    for (int i = tid; i < NBINS; i += 1024) {
        unsigned sfx = hist[i];
        unsigned nxt = (i + 1 < NBINS) ? hist[i + 1] : 0u;
        if (sfx >= (unsigned)MAXDET && nxt < (unsigned)MAXDET) s_thr = i;
    }
    __syncthreads();
    int thr = s_thr;

    // gather candidates
    for (int i = tid; i < NLOC; i += 1024) {
        unsigned long long k = kb[i];
        float s = __uint_as_float((unsigned int)(k >> 32));
        int bu = (int)(s * (float)NBINS);
        bu = min(NBINS - 1, max(0, bu));
        if (bu >= thr) {
            int pos = atomicAdd(&s_cnt, 1);
            if (pos < CAND) cand[pos] = k;
        }
    }
    __syncthreads();
    int cnt = min(s_cnt, CAND);
    for (int i = cnt + tid; i < CAND; i += 1024) cand[i] = 0ull;
    __syncthreads();

    // bitonic sort descending, 4096 elements
    for (int k2 = 2; k2 <= CAND; k2 <<= 1) {
        for (int j = k2 >> 1; j > 0; j >>= 1) {
            for (int i = tid; i < CAND; i += 1024) {
                int ixj = i ^ j;
                if (ixj > i) {
                    unsigned long long a = cand[i];
                    unsigned long long c = cand[ixj];
                    bool up = ((i & k2) == 0);  // region wants descending
                    if (up ? (a < c) : (a > c)) {
                        cand[i] = c;
                        cand[ixj] = a;
                    }
                }
            }
            __syncthreads();
        }
    }

    if (tid < MAXDET) {
        unsigned long long k = cand[tid];
        g_tk_loc[b * MAXDET + tid] = (int)(~(unsigned int)(k & 0xFFFFFFFFull));
        g_tk_score[b * MAXDET + tid] = __uint_as_float((unsigned int)(k >> 32));
    }
}

// ------------------------- K3: decode selected boxes -------------------------
__global__ void k_decode(Ptrs P) {
    int t = blockIdx.x * blockDim.x + threadIdx.x;
    if (t >= BATCH * MAXDET) return;
    int b = t / MAXDET;

    int loc = g_tk_loc[t];
    int lvl, hh, local, stride, h;
    loc_to_level(loc, lvl, hh, local, stride, h);
    int y = local / h;
    int x = local - y * h;
    float cx = (float)(x * stride + stride / 2);
    float cy = (float)(y * stride + stride / 2);

    // class = argmax over 15 cls logits (+1); strict > keeps first index on ties
    {
        const float* pc = P.cls[lvl] + (size_t)b * 15 * hh + local;
        float m = pc[0];
        int am = 0;
#pragma unroll
        for (int c = 1; c < 15; c++) {
            float v = pc[(size_t)c * hh];
            if (v > m) { m = v; am = c; }
        }
        g_tk_cls[t] = am + 1;
    }

    // theta = (argmax tc + 1) * 10 + tr_logit
    float theta;
    {
        const float* pt = P.tc[lvl] + (size_t)b * 18 * hh + local;
        float m = pt[0];
        int am = 0;
#pragma unroll
        for (int c = 1; c < 18; c++) {
            float v = pt[(size_t)c * hh];
            if (v > m) { m = v; am = c; }
        }
        float trv = P.tr[lvl][(size_t)b * hh + local];
        theta = (float)(am + 1) * 10.0f + trv;
    }

    const float* pr = P.reg[lvl] + (size_t)b * 5 * hh + local;
    float sf = (float)stride;
    float r0 = __fmul_rn(pr[0], sf);
    float r1 = __fmul_rn(pr[(size_t)1 * hh], sf);
    float r2 = __fmul_rn(pr[(size_t)2 * hh], sf);
    float r3 = __fmul_rn(pr[(size_t)3 * hh], sf);
    float x1 = __fsub_rn(cx, r0);
    float y1 = __fsub_rn(cy, r1);
    float x2 = __fadd_rn(cx, r2);
    float y2 = __fadd_rn(cy, r3);

    g_tk_box[t * 5 + 0] = x1;
    g_tk_box[t * 5 + 1] = y1;
    g_tk_box[t * 5 + 2] = x2;
    g_tk_box[t * 5 + 3] = y2;
    g_tk_box[t * 5 + 4] = theta;
    g_nms_box[t * 4 + 0] = x1;
    g_nms_box[t * 4 + 1] = y1;
    g_nms_box[t * 4 + 2] = x2;
    g_nms_box[t * 4 + 3] = y2;
    g_tk_valid[t] = (g_tk_score[t] >= 0.05f) ? 1 : 0;
}

// ------------------------- K4: IoU suppression bitmask -------------------------
__global__ void __launch_bounds__(256) k_masks() {
    __shared__ float sb[MAXDET][4];
    __shared__ float sa[MAXDET];

    int b = blockIdx.x >> 2;
    int chunk = blockIdx.x & 3;
    int tid = threadIdx.x;

    const float* Bx = g_nms_box + (size_t)b * MAXDET * 4;
    for (int i = tid; i < MAXDET; i += 256) {
        float x1 = Bx[i * 4 + 0], y1 = Bx[i * 4 + 1];
        float x2 = Bx[i * 4 + 2], y2 = Bx[i * 4 + 3];
        sb[i][0] = x1; sb[i][1] = y1; sb[i][2] = x2; sb[i][3] = y2;
        sa[i] = __fmul_rn(fmaxf(__fsub_rn(x2, x1), 0.0f), fmaxf(__fsub_rn(y2, y1), 0.0f));
    }
    __syncthreads();

    int i = chunk * 256 + tid;
    if (i >= MAXDET) return;
    float x1i = sb[i][0], y1i = sb[i][1], x2i = sb[i][2], y2i = sb[i][3];
    float ai = sa[i];

    unsigned long long* mrow = g_mask + ((size_t)b * MAXDET + i) * 16;
#pragma unroll 1
    for (int w = 0; w < 16; w++) {
        unsigned long long bits = 0ull;
        int j0 = w * 64;
#pragma unroll 4
        for (int jj = 0; jj < 64; jj++) {
            int j = j0 + jj;
            if (j < MAXDET && j > i) {
                float iw = fmaxf(__fsub_rn(fminf(x2i, sb[j][2]), fmaxf(x1i, sb[j][0])), 0.0f);
                float ih = fmaxf(__fsub_rn(fminf(y2i, sb[j][3]), fmaxf(y1i, sb[j][1])), 0.0f);
                float inter = __fmul_rn(iw, ih);
                float un = __fsub_rn(__fadd_rn(ai, sa[j]), inter);
                float iou = __fdiv_rn(inter, fmaxf(un, 1e-8f));
                if (iou > 0.3f) bits |= (1ull << jj);
            }
        }
        mrow[w] = bits;
    }
}

// ------------------------- K5: serial NMS scan + output write -------------------------
__global__ void __launch_bounds__(1024) k_nms(float* __restrict__ out) {
    extern __shared__ unsigned long long sm[];  // 16000 words (125 KB)
    __shared__ unsigned char sval[MAXDET];
    __shared__ unsigned char skeep[MAXDET];

    int b = blockIdx.x;
    int tid = threadIdx.x;

    const unsigned long long* mb = g_mask + (size_t)b * MAXDET * 16;
    for (int i = tid; i < MAXDET * 16; i += 1024) sm[i] = mb[i];
    for (int i = tid; i < MAXDET; i += 1024) sval[i] = g_tk_valid[b * MAXDET + i];
    __syncthreads();

    if (tid < 32) {
        unsigned long long rem[16];
#pragma unroll
        for (int u = 0; u < 16; u++) rem[u] = 0ull;

#pragma unroll
        for (int w = 0; w < 16; w++) {
            unsigned long long rw = rem[w];
            int lim = min(64, MAXDET - w * 64);
            for (int bit = 0; bit < lim; bit++) {
                int i = w * 64 + bit;
                bool kept = sval[i] && !((rw >> bit) & 1ull);
                skeep[i] = kept ? 1 : 0;
                if (kept) {
                    const unsigned long long* row = &sm[i * 16];
#pragma unroll
                    for (int u = 0; u < 16; u++) rem[u] |= row[u];
                    rw = rem[w];
                }
            }
        }
    }
    __syncthreads();

    // output layout: scores [16*1000] | classes [16*1000] | boxes [16*1000*5]
    float* out_s = out;
    float* out_c = out + BATCH * MAXDET;
    float* out_b = out + 2 * BATCH * MAXDET;
    for (int i = tid; i < MAXDET; i += 1024) {
        int g = b * MAXDET + i;
        bool k = skeep[i] != 0;
        out_s[g] = k ? g_tk_score[g] : 0.0f;
        out_c[g] = k ? (float)g_tk_cls[g] : 0.0f;
#pragma unroll
        for (int u = 0; u < 5; u++) out_b[(size_t)g * 5 + u] = k ? g_tk_box[g * 5 + u] : 0.0f;
    }
}

// ------------------------- launch -------------------------
extern "C" void kernel_launch(void* const* d_in, const int* in_sizes, int n_in,
                              void* d_out, int out_size) {
    Ptrs P;
    for (int l = 0; l < 5; l++) {
        P.cls[l] = (const float*)d_in[l];
        P.reg[l] = (const float*)d_in[5 + l];
        P.tc[l]  = (const float*)d_in[10 + l];
        P.tr[l]  = (const float*)d_in[15 + l];
    }
    float* out = (float*)d_out;

    static bool attr_set = false;
    // (idempotent; not a stream op, safe under capture)
    cudaFuncSetAttribute(k_nms, cudaFuncAttributeMaxDynamicSharedMemorySize,
                         MAXDET * 16 * (int)sizeof(unsigned long long) + 1024);
    (void)attr_set;

    int total = BATCH * NLOC;
    k_scores<<<(total + 255) / 256, 256>>>(P);
    k_select<<<BATCH, 1024>>>();
    k_decode<<<(BATCH * MAXDET + 255) / 256, 256>>>(P);
    k_masks<<<BATCH * 4, 256>>>();
    k_nms<<<BATCH, 1024, MAXDET * 16 * (int)sizeof(unsigned long long)>>>(out);

    (void)in_sizes; (void)n_in; (void)out_size;
}

// round 2
// speedup vs baseline: 2.1265x; 2.1265x over previous
#include <cuda_runtime.h>
#include <cuda_bf16.h>
#include <math.h>

#define NLOC 49104
#define BATCH 16
#define MAXDET 1000
#define CAND 2048
#define NBINS 2048

// Levels: HS = 192,96,48,24,12 ; strides 8,16,32,64,128
// offsets: 0, 36864, 46080, 48384, 48960, 49104

struct Ptrs {
    const float* cls[5];
    const float* reg[5];
    const float* tc[5];
    const float* tr[5];
};

// ------------------------- scratch -------------------------
__device__ unsigned long long g_keys[BATCH * NLOC];        // (flip(m_bits), ~loc)
__device__ unsigned long long g_cand[BATCH * CAND];        // candidate m-keys
__device__ int                g_ccnt[BATCH];
__device__ unsigned long long g_cand2[BATCH * CAND];       // (score_bits, ~loc)
__device__ int                g_tk_loc[BATCH * MAXDET];
__device__ float              g_tk_score[BATCH * MAXDET];
__device__ float              g_tk_box[BATCH * MAXDET * 5];
__device__ int                g_tk_cls[BATCH * MAXDET];
__device__ unsigned char      g_tk_valid[BATCH * MAXDET];
__device__ float              g_nms_box[BATCH * MAXDET * 4];
__device__ unsigned long long g_mask[BATCH * MAXDET * 16]; // 2 MB

// ------------------------- helpers -------------------------
__device__ __forceinline__ void loc_to_level(int loc, int& lvl, int& hh, int& local,
                                             int& stride, int& h) {
    if (loc < 36864)      { lvl = 0; hh = 36864; local = loc;         stride = 8;   h = 192; }
    else if (loc < 46080) { lvl = 1; hh = 9216;  local = loc - 36864; stride = 16;  h = 96;  }
    else if (loc < 48384) { lvl = 2; hh = 2304;  local = loc - 46080; stride = 32;  h = 48;  }
    else if (loc < 48960) { lvl = 3; hh = 576;   local = loc - 48384; stride = 64;  h = 24;  }
    else                  { lvl = 4; hh = 144;   local = loc - 48960; stride = 128; h = 12;  }
}

// monotone float -> uint map (order-preserving)
__device__ __forceinline__ unsigned int flip_f32(float f) {
    unsigned int u = __float_as_uint(f);
    return (u & 0x80000000u) ? ~u : (u | 0x80000000u);
}
__device__ __forceinline__ float unflip_f32(unsigned int mk) {
    unsigned int u = (mk & 0x80000000u) ? (mk ^ 0x80000000u) : ~mk;
    return __uint_as_float(u);
}

// ------------------------- K1: max logit -> m-key (no sigmoid) -------------------------
__global__ void k_scores(Ptrs P) {
    int gid = blockIdx.x * blockDim.x + threadIdx.x;
    if (gid >= BATCH * NLOC) return;
    int b = gid / NLOC;
    int loc = gid - b * NLOC;

    int lvl, hh, local, stride, h;
    loc_to_level(loc, lvl, hh, local, stride, h);

    const float* q = P.cls[lvl] + (size_t)b * 15 * hh + local;
    float m = q[0];
#pragma unroll
    for (int c = 1; c < 15; c++) m = fmaxf(m, q[(size_t)c * hh]);

    unsigned int mk = flip_f32(m);
    g_keys[gid] = ((unsigned long long)mk << 32) | (unsigned int)(~(unsigned int)loc);
}

// ------------------------- K2: candidate selection via 2-level histogram -------------------------
__global__ void __launch_bounds__(1024) k_select() {
    __shared__ unsigned int hist[NBINS];
    __shared__ int s_thrc, s_above, s_thrr, s_cnt;

    int b = blockIdx.x;
    int tid = threadIdx.x;
    const unsigned long long* kb = g_keys + (size_t)b * NLOC;

    hist[tid] = 0u; hist[tid + 1024] = 0u;
    if (tid == 0) { s_cnt = 0; s_thrc = 0; s_above = 0; s_thrr = 0; }
    __syncthreads();

    // coarse histogram on top 11 bits of flipped m
    for (int i = tid; i < NLOC; i += 1024)
        atomicAdd(&hist[(unsigned int)(kb[i] >> 53)], 1u);
    __syncthreads();

    // suffix scan
    for (int off = 1; off < NBINS; off <<= 1) {
        unsigned v0 = hist[tid]        + ((tid + off        < NBINS) ? hist[tid + off]        : 0u);
        unsigned v1 = hist[tid + 1024] + ((tid + 1024 + off < NBINS) ? hist[tid + 1024 + off] : 0u);
        __syncthreads();
        hist[tid] = v0; hist[tid + 1024] = v1;
        __syncthreads();
    }
    for (int i = tid; i < NBINS; i += 1024) {
        unsigned sfx = hist[i];
        unsigned nxt = (i + 1 < NBINS) ? hist[i + 1] : 0u;
        if (sfx >= (unsigned)MAXDET && nxt < (unsigned)MAXDET) { s_thrc = i; s_above = (int)nxt; }
    }
    __syncthreads();
    int thrc = s_thrc;
    int above = s_above;
    __syncthreads();

    // refined histogram: bits [20:10] within coarse bucket thrc
    hist[tid] = 0u; hist[tid + 1024] = 0u;
    __syncthreads();
    for (int i = tid; i < NLOC; i += 1024) {
        unsigned mk = (unsigned int)(kb[i] >> 32);
        if ((mk >> 21) == (unsigned)thrc) atomicAdd(&hist[(mk >> 10) & 0x7FFu], 1u);
    }
    __syncthreads();
    for (int off = 1; off < NBINS; off <<= 1) {
        unsigned v0 = hist[tid]        + ((tid + off        < NBINS) ? hist[tid + off]        : 0u);
        unsigned v1 = hist[tid + 1024] + ((tid + 1024 + off < NBINS) ? hist[tid + 1024 + off] : 0u);
        __syncthreads();
        hist[tid] = v0; hist[tid + 1024] = v1;
        __syncthreads();
    }
    int extra = MAXDET - above;   // >= 1
    for (int i = tid; i < NBINS; i += 1024) {
        int sfx = (int)hist[i];
        int nxt = (i + 1 < NBINS) ? (int)hist[i + 1] : 0;
        if (sfx >= extra && nxt < extra) s_thrr = i;
    }
    __syncthreads();

    unsigned int T = ((unsigned)thrc << 21) | ((unsigned)s_thrr << 10);
    unsigned int Tm = (T >= 4096u) ? (T - 4096u) : 0u;  // tie-safety margin (>>25 ulps)

    for (int i = tid; i < NLOC; i += 1024) {
        unsigned long long k = kb[i];
        if ((unsigned int)(k >> 32) >= Tm) {
            int pos = atomicAdd(&s_cnt, 1);
            if (pos < CAND) g_cand[b * CAND + pos] = k;
        }
    }
    __syncthreads();
    if (tid == 0) g_ccnt[b] = min(s_cnt, CAND);
}

// ------------------------- K3: exact sigmoid for candidates only -------------------------
__global__ void k_escore() {
    int t = blockIdx.x * blockDim.x + threadIdx.x;
    if (t >= BATCH * CAND) return;
    int b = t / CAND;
    int sl = t - b * CAND;

    unsigned long long outk = 0ull;
    if (sl < g_ccnt[b]) {
        unsigned long long k = g_cand[t];
        float m = unflip_f32((unsigned int)(k >> 32));
        double s = 1.0 / (1.0 + exp(-(double)m));
        unsigned int bits = __float_as_uint((float)s);
        outk = ((unsigned long long)bits << 32) | (k & 0xFFFFFFFFull);
    }
    g_cand2[t] = outk;
}

// ------------------------- K4: bitonic sort 2048 -> top-1000 -------------------------
__global__ void __launch_bounds__(1024) k_sort() {
    __shared__ unsigned long long c[CAND];
    int b = blockIdx.x;
    int tid = threadIdx.x;

    c[tid] = g_cand2[b * CAND + tid];
    c[tid + 1024] = g_cand2[b * CAND + tid + 1024];
    __syncthreads();

    for (int k2 = 2; k2 <= CAND; k2 <<= 1) {
        for (int j = k2 >> 1; j > 0; j >>= 1) {
            for (int i = tid; i < CAND; i += 1024) {
                int ixj = i ^ j;
                if (ixj > i) {
                    unsigned long long a = c[i], d = c[ixj];
                    bool up = ((i & k2) == 0);
                    if (up ? (a < d) : (a > d)) { c[i] = d; c[ixj] = a; }
                }
            }
            __syncthreads();
        }
    }

    if (tid < MAXDET) {
        unsigned long long k = c[tid];
        g_tk_loc[b * MAXDET + tid] = (int)(~(unsigned int)(k & 0xFFFFFFFFull));
        g_tk_score[b * MAXDET + tid] = __uint_as_float((unsigned int)(k >> 32));
    }
}

// ------------------------- K5: decode selected boxes -------------------------
__global__ void k_decode(Ptrs P) {
    int t = blockIdx.x * blockDim.x + threadIdx.x;
    if (t >= BATCH * MAXDET) return;
    int b = t / MAXDET;

    int loc = g_tk_loc[t];
    int lvl, hh, local, stride, h;
    loc_to_level(loc, lvl, hh, local, stride, h);
    int y = local / h;
    int x = local - y * h;
    float cx = (float)(x * stride + stride / 2);
    float cy = (float)(y * stride + stride / 2);

    {
        const float* pc = P.cls[lvl] + (size_t)b * 15 * hh + local;
        float m = pc[0]; int am = 0;
#pragma unroll
        for (int c = 1; c < 15; c++) {
            float v = pc[(size_t)c * hh];
            if (v > m) { m = v; am = c; }
        }
        g_tk_cls[t] = am + 1;
    }

    float theta;
    {
        const float* pt = P.tc[lvl] + (size_t)b * 18 * hh + local;
        float m = pt[0]; int am = 0;
#pragma unroll
        for (int c = 1; c < 18; c++) {
            float v = pt[(size_t)c * hh];
            if (v > m) { m = v; am = c; }
        }
        float trv = P.tr[lvl][(size_t)b * hh + local];
        theta = (float)(am + 1) * 10.0f + trv;
    }

    const float* pr = P.reg[lvl] + (size_t)b * 5 * hh + local;
    float sf = (float)stride;
    float r0 = __fmul_rn(pr[0], sf);
    float r1 = __fmul_rn(pr[(size_t)1 * hh], sf);
    float r2 = __fmul_rn(pr[(size_t)2 * hh], sf);
    float r3 = __fmul_rn(pr[(size_t)3 * hh], sf);
    float x1 = __fsub_rn(cx, r0);
    float y1 = __fsub_rn(cy, r1);
    float x2 = __fadd_rn(cx, r2);
    float y2 = __fadd_rn(cy, r3);

    g_tk_box[t * 5 + 0] = x1;
    g_tk_box[t * 5 + 1] = y1;
    g_tk_box[t * 5 + 2] = x2;
    g_tk_box[t * 5 + 3] = y2;
    g_tk_box[t * 5 + 4] = theta;
    g_nms_box[t * 4 + 0] = x1;
    g_nms_box[t * 4 + 1] = y1;
    g_nms_box[t * 4 + 2] = x2;
    g_nms_box[t * 4 + 3] = y2;
    g_tk_valid[t] = (g_tk_score[t] >= 0.05f) ? 1 : 0;
}

// ------------------------- K6: tiled IoU mask (64x64 tiles) -------------------------
__global__ void __launch_bounds__(64) k_masks() {
    int jt = blockIdx.x;   // j word (0..15)
    int it = blockIdx.y;   // i tile (0..15)
    int b  = blockIdx.z;
    int tid = threadIdx.x;
    int i = it * 64 + tid;

    if (jt < it) {
        if (i < MAXDET) g_mask[((size_t)b * MAXDET + i) * 16 + jt] = 0ull;
        return;
    }

    __shared__ float jx1[64], jy1[64], jx2[64], jy2[64], ja[64];
    int j0 = jt * 64;
    int lim = min(64, MAXDET - j0);
    if (tid < lim) {
        const float* Bx = g_nms_box + ((size_t)b * MAXDET + j0 + tid) * 4;
        float x1 = Bx[0], y1 = Bx[1], x2 = Bx[2], y2 = Bx[3];
        jx1[tid] = x1; jy1[tid] = y1; jx2[tid] = x2; jy2[tid] = y2;
        ja[tid] = __fmul_rn(fmaxf(__fsub_rn(x2, x1), 0.0f), fmaxf(__fsub_rn(y2, y1), 0.0f));
    }
    __syncthreads();
    if (i >= MAXDET) return;

    const float* Bi = g_nms_box + ((size_t)b * MAXDET + i) * 4;
    float x1i = Bi[0], y1i = Bi[1], x2i = Bi[2], y2i = Bi[3];
    float ai = __fmul_rn(fmaxf(__fsub_rn(x2i, x1i), 0.0f), fmaxf(__fsub_rn(y2i, y1i), 0.0f));

    unsigned long long bits = 0ull;
    int jjstart = (jt == it) ? (tid + 1) : 0;
    for (int jj = jjstart; jj < lim; jj++) {
        float iw = fmaxf(__fsub_rn(fminf(x2i, jx2[jj]), fmaxf(x1i, jx1[jj])), 0.0f);
        float ih = fmaxf(__fsub_rn(fminf(y2i, jy2[jj]), fmaxf(y1i, jy1[jj])), 0.0f);
        float inter = __fmul_rn(iw, ih);
        float un = fmaxf(__fsub_rn(__fadd_rn(ai, ja[jj]), inter), 1e-8f);
        float t = __fmul_rn(0.3f, un);
        bool set;
        if (inter > __fmul_rn(t, 1.000001f))      set = true;
        else if (inter < __fmul_rn(t, 0.999999f)) set = false;
        else set = (__fdiv_rn(inter, un) > 0.3f);  // ambiguous band: exact division
        bits |= ((unsigned long long)set) << jj;
    }
    g_mask[((size_t)b * MAXDET + i) * 16 + jt] = bits;
}

// ------------------------- K7: serial NMS scan + output write -------------------------
__global__ void __launch_bounds__(1024) k_nms(float* __restrict__ out) {
    extern __shared__ unsigned long long sm[];  // 16000 words (125 KB)
    __shared__ unsigned char sval[MAXDET];
    __shared__ unsigned char skeep[MAXDET];

    int b = blockIdx.x;
    int tid = threadIdx.x;

    const unsigned long long* mb = g_mask + (size_t)b * MAXDET * 16;
    for (int i = tid; i < MAXDET * 16; i += 1024) sm[i] = mb[i];
    for (int i = tid; i < MAXDET; i += 1024) sval[i] = g_tk_valid[b * MAXDET + i];
    __syncthreads();

    if (tid < 32) {
        unsigned long long rem[16];
#pragma unroll
        for (int u = 0; u < 16; u++) rem[u] = 0ull;

#pragma unroll
        for (int w = 0; w < 16; w++) {
            unsigned long long rw = rem[w];
            int lim = min(64, MAXDET - w * 64);
            for (int bit = 0; bit < lim; bit++) {
                int i = w * 64 + bit;
                bool kept = sval[i] && !((rw >> bit) & 1ull);
                skeep[i] = kept ? 1 : 0;
                if (kept) {
                    const unsigned long long* row = &sm[i * 16];
#pragma unroll
                    for (int u = 0; u < 16; u++) rem[u] |= row[u];
                    rw = rem[w];
                }
            }
        }
    }
    __syncthreads();

    float* out_s = out;
    float* out_c = out + BATCH * MAXDET;
    float* out_b = out + 2 * BATCH * MAXDET;
    for (int i = tid; i < MAXDET; i += 1024) {
        int g = b * MAXDET + i;
        bool k = skeep[i] != 0;
        out_s[g] = k ? g_tk_score[g] : 0.0f;
        out_c[g] = k ? (float)g_tk_cls[g] : 0.0f;
#pragma unroll
        for (int u = 0; u < 5; u++) out_b[(size_t)g * 5 + u] = k ? g_tk_box[g * 5 + u] : 0.0f;
    }
}

// ------------------------- launch -------------------------
extern "C" void kernel_launch(void* const* d_in, const int* in_sizes, int n_in,
                              void* d_out, int out_size) {
    Ptrs P;
    for (int l = 0; l < 5; l++) {
        P.cls[l] = (const float*)d_in[l];
        P.reg[l] = (const float*)d_in[5 + l];
        P.tc[l]  = (const float*)d_in[10 + l];
        P.tr[l]  = (const float*)d_in[15 + l];
    }
    float* out = (float*)d_out;

    cudaFuncSetAttribute(k_nms, cudaFuncAttributeMaxDynamicSharedMemorySize,
                         MAXDET * 16 * (int)sizeof(unsigned long long) + 4096);

    int total = BATCH * NLOC;
    k_scores<<<(total + 255) / 256, 256>>>(P);
    k_select<<<BATCH, 1024>>>();
    k_escore<<<(BATCH * CAND + 255) / 256, 256>>>();
    k_sort<<<BATCH, 1024>>>();
    k_decode<<<(BATCH * MAXDET + 255) / 256, 256>>>(P);
    k_masks<<<dim3(16, 16, BATCH), 64>>>();
    k_nms<<<BATCH, 1024, MAXDET * 16 * (int)sizeof(unsigned long long)>>>(out);

    (void)in_sizes; (void)n_in; (void)out_size;
}